// round 10
// baseline (speedup 1.0000x reference)
#include <cuda_runtime.h>
#include <cstdint>

#define N_NODES 65536
#define N_EDGES 524288
#define DIM     512

// Scratch: Y = Adj @ X  (fp32, 128 MB) — static device global (no allocs allowed)
__device__ float g_Y[(size_t)N_NODES * DIM];
// OR of odd 32-bit words of the row-index buffer: ==0  <=>  indices are int64
__device__ unsigned int g_or_hi;

// ---------------------------------------------------------------------------
// Kernel 0: zero Y scratch + reset dtype-detect accumulator
// ---------------------------------------------------------------------------
__global__ void __launch_bounds__(256) zero_kernel() {
    const size_t n4 = (size_t)N_NODES * DIM / 4;
    float4* p = reinterpret_cast<float4*>(g_Y);
    float4 z = make_float4(0.f, 0.f, 0.f, 0.f);
    for (size_t i = (size_t)blockIdx.x * blockDim.x + threadIdx.x; i < n4;
         i += (size_t)gridDim.x * blockDim.x)
        p[i] = z;
    if (blockIdx.x == 0 && threadIdx.x == 0) g_or_hi = 0u;
}

// ---------------------------------------------------------------------------
// Kernel 1: detect int32 vs int64 indices.
// Reads only the first N_EDGES 32-bit words (always in-bounds for both dtypes).
// int64 case: odd words are high halves of entries 0..N_EDGES/2-1 -> all 0.
// int32 case: odd words are random indices in [0,65536) -> OR != 0 w.p. ~1.
// ---------------------------------------------------------------------------
__global__ void __launch_bounds__(256) detect_kernel(const unsigned int* __restrict__ rowu) {
    unsigned int v = 0;
    for (int i = blockIdx.x * blockDim.x + threadIdx.x; i < N_EDGES / 2;
         i += gridDim.x * blockDim.x)
        v |= rowu[2 * i + 1];
    // warp reduce
    #pragma unroll
    for (int s = 16; s > 0; s >>= 1) v |= __shfl_xor_sync(0xFFFFFFFFu, v, s);
    if ((threadIdx.x & 31) == 0 && v) atomicOr(&g_or_hi, v);
}

// ---------------------------------------------------------------------------
// Kernel 2: scatter  Y[row[e]] += vals[e] * x[col[e]]
// One warp per edge; lane l handles float4 chunks l, l+32, l+64, l+96.
// Atomic addresses within a warp are consecutive -> coalesced 128B RMW groups.
// ---------------------------------------------------------------------------
__global__ void __launch_bounds__(256) scatter_kernel(const float* __restrict__ x,
                                                      const void*  __restrict__ rowp,
                                                      const void*  __restrict__ colp,
                                                      const float* __restrict__ vals) {
    const bool is64 = (g_or_hi == 0u);
    int e    = blockIdx.x * (blockDim.x >> 5) + (threadIdx.x >> 5);
    int lane = threadIdx.x & 31;
    if (e >= N_EDGES) return;

    int r, c;
    if (is64) {
        r = (int)reinterpret_cast<const long long*>(rowp)[e];
        c = (int)reinterpret_cast<const long long*>(colp)[e];
    } else {
        r = reinterpret_cast<const int*>(rowp)[e];
        c = reinterpret_cast<const int*>(colp)[e];
    }
    const float v = vals[e];

    const float4* xs = reinterpret_cast<const float4*>(x + (size_t)c * DIM);
    float* yd = g_Y + (size_t)r * DIM;

    #pragma unroll
    for (int i = 0; i < 4; i++) {
        int c4 = lane + 32 * i;          // float4 index within the row
        float4 t = xs[c4];
        int base = c4 * 4;
        atomicAdd(&yd[base + 0], v * t.x);
        atomicAdd(&yd[base + 1], v * t.y);
        atomicAdd(&yd[base + 2], v * t.z);
        atomicAdd(&yd[base + 3], v * t.w);
    }
}

// ---------------------------------------------------------------------------
// Kernel 3: out = Y @ W^T   (M=65536, N=512, K=512, all fp32, K-contiguous)
// Classic 128x128 block tile, K-step 8, double-buffered SMEM, 8x8 per thread.
// blockIdx.x = N-tile (4 values, fastest) so consecutive blocks reuse the same
// Y rows through L2 -> Y streamed from HBM ~once.
// ---------------------------------------------------------------------------
__global__ void __launch_bounds__(256) gemm_kernel(const float* __restrict__ W,
                                                   float* __restrict__ out) {
    __shared__ float As[2][8][128];
    __shared__ float Bs[2][8][128];

    const int bn = blockIdx.x;   // 0..3
    const int bm = blockIdx.y;   // 0..511
    const int tid = threadIdx.x;

    // loader mapping: 128 rows x 8 k = 1024 floats = 256 threads x float4
    const int lrow = tid >> 1;
    const int lk   = (tid & 1) * 4;
    const float* ag = g_Y + ((size_t)(bm * 128 + lrow)) * DIM + lk;
    const float* bg = W   + ((size_t)(bn * 128 + lrow)) * DIM + lk;

    // compute mapping: 16x16 threads, 8x8 micro-tile each
    const int tx = tid & 15, ty = tid >> 4;
    const int rm = ty * 8, rn = tx * 8;

    float acc[8][8];
    #pragma unroll
    for (int i = 0; i < 8; i++)
        #pragma unroll
        for (int j = 0; j < 8; j++) acc[i][j] = 0.f;

    // prime buffer 0
    {
        float4 a = *reinterpret_cast<const float4*>(ag);
        float4 b = *reinterpret_cast<const float4*>(bg);
        As[0][lk + 0][lrow] = a.x; As[0][lk + 1][lrow] = a.y;
        As[0][lk + 2][lrow] = a.z; As[0][lk + 3][lrow] = a.w;
        Bs[0][lk + 0][lrow] = b.x; Bs[0][lk + 1][lrow] = b.y;
        Bs[0][lk + 2][lrow] = b.z; Bs[0][lk + 3][lrow] = b.w;
    }
    __syncthreads();

    int buf = 0;
    const int KT = DIM / 8;   // 64
    #pragma unroll 1
    for (int kt = 0; kt < KT; kt++) {
        float4 an, bn4;
        const bool more = (kt + 1 < KT);
        if (more) {
            an  = *reinterpret_cast<const float4*>(ag + (kt + 1) * 8);
            bn4 = *reinterpret_cast<const float4*>(bg + (kt + 1) * 8);
        }

        #pragma unroll
        for (int kk = 0; kk < 8; kk++) {
            float4 a0 = *reinterpret_cast<const float4*>(&As[buf][kk][rm]);
            float4 a1 = *reinterpret_cast<const float4*>(&As[buf][kk][rm + 4]);
            float4 b0 = *reinterpret_cast<const float4*>(&Bs[buf][kk][rn]);
            float4 b1 = *reinterpret_cast<const float4*>(&Bs[buf][kk][rn + 4]);
            float av[8] = {a0.x, a0.y, a0.z, a0.w, a1.x, a1.y, a1.z, a1.w};
            float bv[8] = {b0.x, b0.y, b0.z, b0.w, b1.x, b1.y, b1.z, b1.w};
            #pragma unroll
            for (int i = 0; i < 8; i++)
                #pragma unroll
                for (int j = 0; j < 8; j++)
                    acc[i][j] += av[i] * bv[j];
        }

        if (more) {
            const int nb = buf ^ 1;
            As[nb][lk + 0][lrow] = an.x;  As[nb][lk + 1][lrow] = an.y;
            As[nb][lk + 2][lrow] = an.z;  As[nb][lk + 3][lrow] = an.w;
            Bs[nb][lk + 0][lrow] = bn4.x; Bs[nb][lk + 1][lrow] = bn4.y;
            Bs[nb][lk + 2][lrow] = bn4.z; Bs[nb][lk + 3][lrow] = bn4.w;
            __syncthreads();
            buf = nb;
        }
    }

    // epilogue: vectorized stores
    float* op = out + (size_t)(bm * 128 + rm) * DIM + bn * 128 + rn;
    #pragma unroll
    for (int i = 0; i < 8; i++) {
        float4 v0 = make_float4(acc[i][0], acc[i][1], acc[i][2], acc[i][3]);
        float4 v1 = make_float4(acc[i][4], acc[i][5], acc[i][6], acc[i][7]);
        *reinterpret_cast<float4*>(op + (size_t)i * DIM)     = v0;
        *reinterpret_cast<float4*>(op + (size_t)i * DIM + 4) = v1;
    }
}

// ---------------------------------------------------------------------------
// kernel_launch: inputs (metadata order): x, weight, row, col, vals
// ---------------------------------------------------------------------------
extern "C" void kernel_launch(void* const* d_in, const int* in_sizes, int n_in,
                              void* d_out, int out_size) {
    const float* x      = (const float*)d_in[0];
    const float* weight = (const float*)d_in[1];
    const void*  row    = d_in[2];
    const void*  col    = d_in[3];
    const float* vals   = (const float*)d_in[4];
    float* out = (float*)d_out;

    (void)in_sizes; (void)n_in; (void)out_size;

    // 0) zero scratch + detector
    zero_kernel<<<512, 256>>>();

    // 1) index dtype detection (int32 vs int64)
    detect_kernel<<<128, 256>>>((const unsigned int*)row);

    // 2) Y = Adj @ X   (warp per edge, 8 edges/block)
    scatter_kernel<<<N_EDGES / 8, 256>>>(x, row, col, vals);

    // 3) out = Y @ W^T
    dim3 grid(DIM / 128, N_NODES / 128);   // (4, 512), N-tile fastest for Y L2 reuse
    gemm_kernel<<<grid, 256>>>(weight, out);
}

// round 13
// speedup vs baseline: 1.3483x; 1.3483x over previous
#include <cuda_runtime.h>
#include <cuda_bf16.h>
#include <cstdint>

#define N_NODES 65536
#define N_EDGES 524288
#define DIM     512
#define K2      1024   // [hi | lo] split K stride

// ---------------------------------------------------------------------------
// Static device scratch (no allocs allowed)
// ---------------------------------------------------------------------------
__device__ float         g_Y  [(size_t)N_NODES * DIM];   // fp32 aggregation buffer
__device__ __nv_bfloat16 g_Ybf[(size_t)N_NODES * K2];    // [Yhi | Ylo] bf16
__device__ __nv_bfloat16 g_Wbf[(size_t)DIM * K2];        // [Whi | Wlo] bf16
__device__ unsigned int  g_or_hi;

// ---------------------------------------------------------------------------
// Kernel 0: zero Y scratch + reset dtype-detect accumulator
// ---------------------------------------------------------------------------
__global__ void __launch_bounds__(256) zero_kernel() {
    const size_t n4 = (size_t)N_NODES * DIM / 4;
    float4* p = reinterpret_cast<float4*>(g_Y);
    float4 z = make_float4(0.f, 0.f, 0.f, 0.f);
    for (size_t i = (size_t)blockIdx.x * blockDim.x + threadIdx.x; i < n4;
         i += (size_t)gridDim.x * blockDim.x)
        p[i] = z;
    if (blockIdx.x == 0 && threadIdx.x == 0) g_or_hi = 0u;
}

// ---------------------------------------------------------------------------
// Kernel 1: detect int32 vs int64 indices (OR of odd 32-bit words == 0 => int64)
// ---------------------------------------------------------------------------
__global__ void __launch_bounds__(256) detect_kernel(const unsigned int* __restrict__ rowu) {
    unsigned int v = 0;
    for (int i = blockIdx.x * blockDim.x + threadIdx.x; i < N_EDGES / 2;
         i += gridDim.x * blockDim.x)
        v |= rowu[2 * i + 1];
    #pragma unroll
    for (int s = 16; s > 0; s >>= 1) v |= __shfl_xor_sync(0xFFFFFFFFu, v, s);
    if ((threadIdx.x & 31) == 0 && v) atomicOr(&g_or_hi, v);
}

// ---------------------------------------------------------------------------
// Kernel 2: scatter  Y[row[e]] += vals[e] * x[col[e]]   (fp32 atomics)
// ---------------------------------------------------------------------------
__global__ void __launch_bounds__(256) scatter_kernel(const float* __restrict__ x,
                                                      const void*  __restrict__ rowp,
                                                      const void*  __restrict__ colp,
                                                      const float* __restrict__ vals) {
    const bool is64 = (g_or_hi == 0u);
    int e    = blockIdx.x * (blockDim.x >> 5) + (threadIdx.x >> 5);
    int lane = threadIdx.x & 31;
    if (e >= N_EDGES) return;

    int r, c;
    if (is64) {
        r = (int)reinterpret_cast<const long long*>(rowp)[e];
        c = (int)reinterpret_cast<const long long*>(colp)[e];
    } else {
        r = reinterpret_cast<const int*>(rowp)[e];
        c = reinterpret_cast<const int*>(colp)[e];
    }
    const float v = vals[e];

    const float4* xs = reinterpret_cast<const float4*>(x + (size_t)c * DIM);
    float* yd = g_Y + (size_t)r * DIM;

    #pragma unroll
    for (int i = 0; i < 4; i++) {
        int c4 = lane + 32 * i;
        float4 t = xs[c4];
        int base = c4 * 4;
        atomicAdd(&yd[base + 0], v * t.x);
        atomicAdd(&yd[base + 1], v * t.y);
        atomicAdd(&yd[base + 2], v * t.z);
        atomicAdd(&yd[base + 3], v * t.w);
    }
}

// ---------------------------------------------------------------------------
// Kernel 3a/3b: split fp32 -> [hi | lo] bf16, row stride K2=1024
// ---------------------------------------------------------------------------
__device__ __forceinline__ void split_body(const float* __restrict__ src,
                                           __nv_bfloat16* __restrict__ dst,
                                           size_t nrows) {
    const size_t n4 = nrows * (DIM / 4);
    for (size_t i = (size_t)blockIdx.x * blockDim.x + threadIdx.x; i < n4;
         i += (size_t)gridDim.x * blockDim.x) {
        float4 v = reinterpret_cast<const float4*>(src)[i];
        size_t e = i * 4;
        size_t row = e >> 9;
        int col = (int)(e & 511);
        float f[4] = {v.x, v.y, v.z, v.w};
        unsigned short h[4], l[4];
        #pragma unroll
        for (int k = 0; k < 4; k++) {
            __nv_bfloat16 hb = __float2bfloat16_rn(f[k]);
            __nv_bfloat16 lb = __float2bfloat16_rn(f[k] - __bfloat162float(hb));
            h[k] = __bfloat16_as_ushort(hb);
            l[k] = __bfloat16_as_ushort(lb);
        }
        uint2 hp, lp;
        hp.x = (uint32_t)h[0] | ((uint32_t)h[1] << 16);
        hp.y = (uint32_t)h[2] | ((uint32_t)h[3] << 16);
        lp.x = (uint32_t)l[0] | ((uint32_t)l[1] << 16);
        lp.y = (uint32_t)l[2] | ((uint32_t)l[3] << 16);
        *reinterpret_cast<uint2*>(dst + row * K2 + col)       = hp;
        *reinterpret_cast<uint2*>(dst + row * K2 + 512 + col) = lp;
    }
}
__global__ void __launch_bounds__(256) split_Y_kernel() {
    split_body(g_Y, g_Ybf, (size_t)N_NODES);
}
__global__ void __launch_bounds__(256) split_W_kernel(const float* __restrict__ W) {
    split_body(W, g_Wbf, (size_t)DIM);
}

// ---------------------------------------------------------------------------
// Kernel 4: mma.sync bf16 GEMM   out[65536,512] = Y2 @ W2^T  (3-term split)
// CTA tile 128x128, BK=32 bf16, 8 warps (4x2) each 32x64.
// Double-buffered SMEM (80B row stride), cp.async overlap, ldmatrix + HMMA.
// K' = 3*512 = 1536 -> 48 chunks of 32.
// ---------------------------------------------------------------------------
#define BKB   64               // 32 bf16 = 64 bytes per row
#define RSTR  80               // padded row stride (conflict-free ldmatrix)

__device__ __forceinline__ uint32_t smem_u32(const void* p) {
    uint32_t a;
    asm("{ .reg .u64 t; cvta.to.shared.u64 t, %1; cvt.u32.u64 %0, t; }"
        : "=r"(a) : "l"(p));
    return a;
}
__device__ __forceinline__ void cp16(uint32_t smem, const void* gmem) {
    asm volatile("cp.async.cg.shared.global [%0], [%1], 16;"
                 :: "r"(smem), "l"(gmem));
}
__device__ __forceinline__ void ldsm4(uint32_t* r, uint32_t addr) {
    asm volatile("ldmatrix.sync.aligned.m8n8.x4.shared.b16 {%0,%1,%2,%3}, [%4];"
                 : "=r"(r[0]), "=r"(r[1]), "=r"(r[2]), "=r"(r[3]) : "r"(addr));
}
__device__ __forceinline__ void mma16816(float* d, const uint32_t* a,
                                         uint32_t b0, uint32_t b1) {
    asm volatile(
        "mma.sync.aligned.m16n8k16.row.col.f32.bf16.bf16.f32 "
        "{%0,%1,%2,%3}, {%4,%5,%6,%7}, {%8,%9}, {%0,%1,%2,%3};"
        : "+f"(d[0]), "+f"(d[1]), "+f"(d[2]), "+f"(d[3])
        : "r"(a[0]), "r"(a[1]), "r"(a[2]), "r"(a[3]), "r"(b0), "r"(b1));
}

__global__ void __launch_bounds__(256) gemm_mma_kernel(float* __restrict__ out) {
    __shared__ char sA[2][128 * RSTR];
    __shared__ char sB[2][128 * RSTR];

    const int tid  = threadIdx.x;
    const int wid  = tid >> 5;
    const int lane = tid & 31;
    const int bn   = blockIdx.x;   // 0..3  (N tiles of 128)
    const int bm   = blockIdx.y;   // 0..511 (M tiles of 128)

    const int wm = (wid >> 1) * 32;   // warp M offset in tile
    const int wn = (wid & 1) * 64;    // warp N offset in tile

    // ---- global load mapping: 512 16B units per tile, 2 per thread ----
    int r0 = tid >> 2, c0 = (tid & 3) * 16;             // unit tid
    int r1 = (tid + 256) >> 2, c1 = c0;                 // unit tid+256
    const char* Ag0 = (const char*)(g_Ybf + (size_t)(bm * 128 + r0) * K2) + c0;
    const char* Ag1 = (const char*)(g_Ybf + (size_t)(bm * 128 + r1) * K2) + c1;
    const char* Bg0 = (const char*)(g_Wbf + (size_t)(bn * 128 + r0) * K2) + c0;
    const char* Bg1 = (const char*)(g_Wbf + (size_t)(bn * 128 + r1) * K2) + c1;
    const int sOffA0 = r0 * RSTR + c0, sOffA1 = r1 * RSTR + c1;

    const uint32_t saA = smem_u32(sA[0]);
    const uint32_t saB = smem_u32(sB[0]);
    const uint32_t STG_A = 128 * RSTR;

    // ---- ldmatrix per-thread row offsets ----
    const int lrow = lane & 15;
    const int lhalf = ((lane >> 4) & 1) * 16;           // byte offset for k8-15
    uint32_t rowA[2], rowB[4];
    #pragma unroll
    for (int mt = 0; mt < 2; mt++)
        rowA[mt] = (uint32_t)((wm + mt * 16 + lrow) * RSTR + lhalf);
    #pragma unroll
    for (int nt = 0; nt < 4; nt++)
        rowB[nt] = (uint32_t)((wn + nt * 16 + lrow) * RSTR + lhalf);

    float acc[2][8][4];
    #pragma unroll
    for (int mt = 0; mt < 2; mt++)
        #pragma unroll
        for (int j = 0; j < 8; j++)
            #pragma unroll
            for (int q = 0; q < 4; q++) acc[mt][j][q] = 0.f;

    // chunk i (0..47): p = i>>4 selects split term, c = i&15 -> k offset
    auto issue_loads = [&](int i, int s) {
        const int p = i >> 4, c = i & 15;
        const int akB = (((p == 2) ? 512 : 0) + c * 32) * 2;   // bytes
        const int bkB = (((p == 1) ? 512 : 0) + c * 32) * 2;
        uint32_t dA = saA + s * STG_A;
        uint32_t dB = saB + s * STG_A;
        cp16(dA + sOffA0, Ag0 + akB);
        cp16(dA + sOffA1, Ag1 + akB);
        cp16(dB + sOffA0, Bg0 + bkB);
        cp16(dB + sOffA1, Bg1 + bkB);
        asm volatile("cp.async.commit_group;");
    };

    // prologue
    issue_loads(0, 0);
    asm volatile("cp.async.wait_group 0;");
    __syncthreads();

    #pragma unroll 1
    for (int i = 0; i < 48; i++) {
        const int s = i & 1;
        if (i < 47) issue_loads(i + 1, s ^ 1);

        const uint32_t bA = saA + s * STG_A;
        const uint32_t bB = saB + s * STG_A;

        #pragma unroll
        for (int kt = 0; kt < 2; kt++) {
            uint32_t af[2][4], bf[4][4];
            #pragma unroll
            for (int mt = 0; mt < 2; mt++)
                ldsm4(af[mt], bA + rowA[mt] + kt * 32);
            #pragma unroll
            for (int nt = 0; nt < 4; nt++)
                ldsm4(bf[nt], bB + rowB[nt] + kt * 32);
            #pragma unroll
            for (int mt = 0; mt < 2; mt++)
                #pragma unroll
                for (int nt = 0; nt < 4; nt++) {
                    mma16816(acc[mt][nt * 2 + 0], af[mt], bf[nt][0], bf[nt][2]);
                    mma16816(acc[mt][nt * 2 + 1], af[mt], bf[nt][1], bf[nt][3]);
                }
        }

        if (i < 47) {
            asm volatile("cp.async.wait_group 0;");
            __syncthreads();
        }
    }

    // ---- epilogue: c frag rows lane>>2 (+8), cols (lane&3)*2 ----
    const int erow = lane >> 2, ecol = (lane & 3) * 2;
    #pragma unroll
    for (int mt = 0; mt < 2; mt++) {
        float* o0 = out + (size_t)(bm * 128 + wm + mt * 16 + erow) * DIM
                        + bn * 128 + wn + ecol;
        float* o1 = o0 + 8 * DIM;
        #pragma unroll
        for (int j = 0; j < 8; j++) {
            *reinterpret_cast<float2*>(o0 + j * 8) =
                make_float2(acc[mt][j][0], acc[mt][j][1]);
            *reinterpret_cast<float2*>(o1 + j * 8) =
                make_float2(acc[mt][j][2], acc[mt][j][3]);
        }
    }
}

// ---------------------------------------------------------------------------
// kernel_launch: inputs (metadata order): x, weight, row, col, vals
// ---------------------------------------------------------------------------
extern "C" void kernel_launch(void* const* d_in, const int* in_sizes, int n_in,
                              void* d_out, int out_size) {
    const float* x      = (const float*)d_in[0];
    const float* weight = (const float*)d_in[1];
    const void*  row    = d_in[2];
    const void*  col    = d_in[3];
    const float* vals   = (const float*)d_in[4];
    float* out = (float*)d_out;

    (void)in_sizes; (void)n_in; (void)out_size;

    // 0) zero scratch + detector
    zero_kernel<<<512, 256>>>();
    // 1) index dtype detection (int32 vs int64)
    detect_kernel<<<128, 256>>>((const unsigned int*)row);
    // 2) W split (independent of scatter)
    split_W_kernel<<<256, 256>>>(weight);
    // 3) Y = Adj @ X
    scatter_kernel<<<N_EDGES / 8, 256>>>(x, row, col, vals);
    // 4) Y split -> bf16 hi/lo
    split_Y_kernel<<<2048, 256>>>();
    // 5) out = Y2 @ W2^T on tensor cores (mma.sync bf16, 3-term split)
    dim3 grid(4, 512);
    gemm_mma_kernel<<<grid, 256>>>(out);
}

// round 14
// speedup vs baseline: 2.8500x; 2.1138x over previous
#include <cuda_runtime.h>
#include <cuda_bf16.h>
#include <cstdint>

#define N_NODES 65536
#define N_EDGES 524288
#define DIM     512
#define K2      1024   // [hi | lo] split K stride

// ---------------------------------------------------------------------------
// Static device scratch (no allocs allowed)
// ---------------------------------------------------------------------------
__device__ __nv_bfloat16 g_Ybf[(size_t)N_NODES * K2];    // [Yhi | Ylo] bf16
__device__ __nv_bfloat16 g_Wbf[(size_t)DIM * K2];        // [Whi | Wlo] bf16
__device__ unsigned int  g_or_hi;
__device__ int           g_cnt   [N_NODES];
__device__ int           g_start [N_NODES];
__device__ int           g_cursor[N_NODES];
__device__ int           g_blk   [256];
__device__ uint2         g_edges [N_EDGES];              // (col, val-bits) CSR order

// ---------------------------------------------------------------------------
// Kernel 0: zero row counters + dtype-detect accumulator
// ---------------------------------------------------------------------------
__global__ void __launch_bounds__(256) init_kernel() {
    int i = blockIdx.x * blockDim.x + threadIdx.x;
    #pragma unroll
    for (int j = 0; j < 4; j++) g_cnt[i * 4 + j] = 0;
    if (i == 0) g_or_hi = 0u;
}

// ---------------------------------------------------------------------------
// Kernel 1: detect int32 vs int64 indices (OR of odd 32-bit words == 0 => int64)
// ---------------------------------------------------------------------------
__global__ void __launch_bounds__(256) detect_kernel(const unsigned int* __restrict__ rowu) {
    unsigned int v = 0;
    for (int i = blockIdx.x * blockDim.x + threadIdx.x; i < N_EDGES / 2;
         i += gridDim.x * blockDim.x)
        v |= rowu[2 * i + 1];
    #pragma unroll
    for (int s = 16; s > 0; s >>= 1) v |= __shfl_xor_sync(0xFFFFFFFFu, v, s);
    if ((threadIdx.x & 31) == 0 && v) atomicOr(&g_or_hi, v);
}

__device__ __forceinline__ int load_idx(const void* p, int e, bool is64) {
    return is64 ? (int)reinterpret_cast<const long long*>(p)[e]
                : reinterpret_cast<const int*>(p)[e];
}

// ---------------------------------------------------------------------------
// Kernel 2: histogram of row indices
// ---------------------------------------------------------------------------
__global__ void __launch_bounds__(256) hist_kernel(const void* __restrict__ rowp) {
    const bool is64 = (g_or_hi == 0u);
    int e = blockIdx.x * blockDim.x + threadIdx.x;
    atomicAdd(&g_cnt[load_idx(rowp, e, is64)], 1);
}

// ---------------------------------------------------------------------------
// Kernels 3a-3c: exclusive scan of g_cnt (65536) -> g_start, g_cursor
// ---------------------------------------------------------------------------
__global__ void __launch_bounds__(256) scan1_kernel() {   // per-block sums
    __shared__ int sh[256];
    int v = g_cnt[blockIdx.x * 256 + threadIdx.x];
    sh[threadIdx.x] = v;
    __syncthreads();
    for (int s = 128; s > 0; s >>= 1) {
        if (threadIdx.x < s) sh[threadIdx.x] += sh[threadIdx.x + s];
        __syncthreads();
    }
    if (threadIdx.x == 0) g_blk[blockIdx.x] = sh[0];
}
__global__ void __launch_bounds__(256) scan2_kernel() {   // scan of 256 block sums
    __shared__ int sh[256];
    int v = g_blk[threadIdx.x];
    sh[threadIdx.x] = v;
    __syncthreads();
    // Hillis-Steele inclusive scan
    for (int d = 1; d < 256; d <<= 1) {
        int t = (threadIdx.x >= d) ? sh[threadIdx.x - d] : 0;
        __syncthreads();
        sh[threadIdx.x] += t;
        __syncthreads();
    }
    g_blk[threadIdx.x] = sh[threadIdx.x] - v;   // exclusive
}
__global__ void __launch_bounds__(256) scan3_kernel() {   // local scan + offset
    __shared__ int sh[256];
    int i = blockIdx.x * 256 + threadIdx.x;
    int v = g_cnt[i];
    sh[threadIdx.x] = v;
    __syncthreads();
    for (int d = 1; d < 256; d <<= 1) {
        int t = (threadIdx.x >= d) ? sh[threadIdx.x - d] : 0;
        __syncthreads();
        sh[threadIdx.x] += t;
        __syncthreads();
    }
    int st = g_blk[blockIdx.x] + sh[threadIdx.x] - v;     // exclusive
    g_start[i]  = st;
    g_cursor[i] = st;
}

// ---------------------------------------------------------------------------
// Kernel 4: reorder edges into CSR order (packed col + val bits)
// ---------------------------------------------------------------------------
__global__ void __launch_bounds__(256) reorder_kernel(const void* __restrict__ rowp,
                                                      const void* __restrict__ colp,
                                                      const float* __restrict__ vals) {
    const bool is64 = (g_or_hi == 0u);
    int e = blockIdx.x * blockDim.x + threadIdx.x;
    int r = load_idx(rowp, e, is64);
    int c = load_idx(colp, e, is64);
    int pos = atomicAdd(&g_cursor[r], 1);
    g_edges[pos] = make_uint2((unsigned)c, __float_as_uint(vals[e]));
}

// ---------------------------------------------------------------------------
// Kernel 5: gather SpMM. One warp per row: acc = sum_e val*x[col], written
// directly as bf16 [hi|lo] split into g_Ybf. No atomics, no fp32 Y buffer.
// ---------------------------------------------------------------------------
__global__ void __launch_bounds__(256) spmm_kernel(const float* __restrict__ x) {
    const int row  = blockIdx.x * 8 + (threadIdx.x >> 5);
    const int lane = threadIdx.x & 31;
    const int s = g_start[row];
    const int e = s + g_cnt[row];

    float4 acc[4];
    #pragma unroll
    for (int j = 0; j < 4; j++) acc[j] = make_float4(0.f, 0.f, 0.f, 0.f);

    int i = s;
    // 2-edge unroll for MLP (8 outstanding LDG.128 per lane pair-step)
    for (; i + 1 < e; i += 2) {
        uint2 p0 = g_edges[i], p1 = g_edges[i + 1];
        const float4* x0 = reinterpret_cast<const float4*>(x + (size_t)p0.x * DIM);
        const float4* x1 = reinterpret_cast<const float4*>(x + (size_t)p1.x * DIM);
        float v0 = __uint_as_float(p0.y), v1 = __uint_as_float(p1.y);
        float4 t0[4], t1[4];
        #pragma unroll
        for (int j = 0; j < 4; j++) { t0[j] = x0[lane + 32 * j]; t1[j] = x1[lane + 32 * j]; }
        #pragma unroll
        for (int j = 0; j < 4; j++) {
            acc[j].x += v0 * t0[j].x + v1 * t1[j].x;
            acc[j].y += v0 * t0[j].y + v1 * t1[j].y;
            acc[j].z += v0 * t0[j].z + v1 * t1[j].z;
            acc[j].w += v0 * t0[j].w + v1 * t1[j].w;
        }
    }
    if (i < e) {
        uint2 p = g_edges[i];
        const float4* xs = reinterpret_cast<const float4*>(x + (size_t)p.x * DIM);
        float v = __uint_as_float(p.y);
        #pragma unroll
        for (int j = 0; j < 4; j++) {
            float4 t = xs[lane + 32 * j];
            acc[j].x += v * t.x; acc[j].y += v * t.y;
            acc[j].z += v * t.z; acc[j].w += v * t.w;
        }
    }

    // epilogue: split fp32 -> bf16 hi/lo, write both halves
    __nv_bfloat16* dst = g_Ybf + (size_t)row * K2;
    #pragma unroll
    for (int j = 0; j < 4; j++) {
        int c4 = lane + 32 * j;
        float f[4] = {acc[j].x, acc[j].y, acc[j].z, acc[j].w};
        unsigned short h[4], l[4];
        #pragma unroll
        for (int k = 0; k < 4; k++) {
            __nv_bfloat16 hb = __float2bfloat16_rn(f[k]);
            __nv_bfloat16 lb = __float2bfloat16_rn(f[k] - __bfloat162float(hb));
            h[k] = __bfloat16_as_ushort(hb);
            l[k] = __bfloat16_as_ushort(lb);
        }
        uint2 hp, lp;
        hp.x = (uint32_t)h[0] | ((uint32_t)h[1] << 16);
        hp.y = (uint32_t)h[2] | ((uint32_t)h[3] << 16);
        lp.x = (uint32_t)l[0] | ((uint32_t)l[1] << 16);
        lp.y = (uint32_t)l[2] | ((uint32_t)l[3] << 16);
        *reinterpret_cast<uint2*>(dst + 4 * c4)       = hp;
        *reinterpret_cast<uint2*>(dst + 512 + 4 * c4) = lp;
    }
}

// ---------------------------------------------------------------------------
// Kernel 6: split W fp32 -> [hi | lo] bf16
// ---------------------------------------------------------------------------
__global__ void __launch_bounds__(256) split_W_kernel(const float* __restrict__ W) {
    const size_t n4 = (size_t)DIM * (DIM / 4);
    for (size_t i = (size_t)blockIdx.x * blockDim.x + threadIdx.x; i < n4;
         i += (size_t)gridDim.x * blockDim.x) {
        float4 v = reinterpret_cast<const float4*>(W)[i];
        size_t e = i * 4;
        size_t row = e >> 9;
        int col = (int)(e & 511);
        float f[4] = {v.x, v.y, v.z, v.w};
        unsigned short h[4], l[4];
        #pragma unroll
        for (int k = 0; k < 4; k++) {
            __nv_bfloat16 hb = __float2bfloat16_rn(f[k]);
            __nv_bfloat16 lb = __float2bfloat16_rn(f[k] - __bfloat162float(hb));
            h[k] = __bfloat16_as_ushort(hb);
            l[k] = __bfloat16_as_ushort(lb);
        }
        uint2 hp, lp;
        hp.x = (uint32_t)h[0] | ((uint32_t)h[1] << 16);
        hp.y = (uint32_t)h[2] | ((uint32_t)h[3] << 16);
        lp.x = (uint32_t)l[0] | ((uint32_t)l[1] << 16);
        lp.y = (uint32_t)l[2] | ((uint32_t)l[3] << 16);
        *reinterpret_cast<uint2*>(g_Wbf + row * K2 + col)       = hp;
        *reinterpret_cast<uint2*>(g_Wbf + row * K2 + 512 + col) = lp;
    }
}

// ---------------------------------------------------------------------------
// Kernel 7: mma.sync bf16 GEMM   out[65536,512] = Y2 @ W2^T  (3-term split)
// CTA tile 128x128, BK=32, 8 warps (4x2) each 32x64, double-buffered cp.async.
// ---------------------------------------------------------------------------
#define RSTR  80               // padded smem row stride (conflict-free ldmatrix)

__device__ __forceinline__ uint32_t smem_u32(const void* p) {
    uint32_t a;
    asm("{ .reg .u64 t; cvta.to.shared.u64 t, %1; cvt.u32.u64 %0, t; }"
        : "=r"(a) : "l"(p));
    return a;
}
__device__ __forceinline__ void cp16(uint32_t smem, const void* gmem) {
    asm volatile("cp.async.cg.shared.global [%0], [%1], 16;"
                 :: "r"(smem), "l"(gmem));
}
__device__ __forceinline__ void ldsm4(uint32_t* r, uint32_t addr) {
    asm volatile("ldmatrix.sync.aligned.m8n8.x4.shared.b16 {%0,%1,%2,%3}, [%4];"
                 : "=r"(r[0]), "=r"(r[1]), "=r"(r[2]), "=r"(r[3]) : "r"(addr));
}
__device__ __forceinline__ void mma16816(float* d, const uint32_t* a,
                                         uint32_t b0, uint32_t b1) {
    asm volatile(
        "mma.sync.aligned.m16n8k16.row.col.f32.bf16.bf16.f32 "
        "{%0,%1,%2,%3}, {%4,%5,%6,%7}, {%8,%9}, {%0,%1,%2,%3};"
        : "+f"(d[0]), "+f"(d[1]), "+f"(d[2]), "+f"(d[3])
        : "r"(a[0]), "r"(a[1]), "r"(a[2]), "r"(a[3]), "r"(b0), "r"(b1));
}

__global__ void __launch_bounds__(256) gemm_mma_kernel(float* __restrict__ out) {
    __shared__ char sA[2][128 * RSTR];
    __shared__ char sB[2][128 * RSTR];

    const int tid  = threadIdx.x;
    const int wid  = tid >> 5;
    const int lane = tid & 31;
    const int bn   = blockIdx.x;   // 0..3  (N tiles of 128)
    const int bm   = blockIdx.y;   // 0..511 (M tiles of 128)

    const int wm = (wid >> 1) * 32;
    const int wn = (wid & 1) * 64;

    int r0 = tid >> 2, c0 = (tid & 3) * 16;
    int r1 = (tid + 256) >> 2, c1 = c0;
    const char* Ag0 = (const char*)(g_Ybf + (size_t)(bm * 128 + r0) * K2) + c0;
    const char* Ag1 = (const char*)(g_Ybf + (size_t)(bm * 128 + r1) * K2) + c1;
    const char* Bg0 = (const char*)(g_Wbf + (size_t)(bn * 128 + r0) * K2) + c0;
    const char* Bg1 = (const char*)(g_Wbf + (size_t)(bn * 128 + r1) * K2) + c1;
    const int sOffA0 = r0 * RSTR + c0, sOffA1 = r1 * RSTR + c1;

    const uint32_t saA = smem_u32(sA[0]);
    const uint32_t saB = smem_u32(sB[0]);
    const uint32_t STG_A = 128 * RSTR;

    const int lrow = lane & 15;
    const int lhalf = ((lane >> 4) & 1) * 16;
    uint32_t rowA[2], rowB[4];
    #pragma unroll
    for (int mt = 0; mt < 2; mt++)
        rowA[mt] = (uint32_t)((wm + mt * 16 + lrow) * RSTR + lhalf);
    #pragma unroll
    for (int nt = 0; nt < 4; nt++)
        rowB[nt] = (uint32_t)((wn + nt * 16 + lrow) * RSTR + lhalf);

    float acc[2][8][4];
    #pragma unroll
    for (int mt = 0; mt < 2; mt++)
        #pragma unroll
        for (int j = 0; j < 8; j++)
            #pragma unroll
            for (int q = 0; q < 4; q++) acc[mt][j][q] = 0.f;

    auto issue_loads = [&](int i, int s) {
        const int p = i >> 4, c = i & 15;
        const int akB = (((p == 2) ? 512 : 0) + c * 32) * 2;
        const int bkB = (((p == 1) ? 512 : 0) + c * 32) * 2;
        uint32_t dA = saA + s * STG_A;
        uint32_t dB = saB + s * STG_A;
        cp16(dA + sOffA0, Ag0 + akB);
        cp16(dA + sOffA1, Ag1 + akB);
        cp16(dB + sOffA0, Bg0 + bkB);
        cp16(dB + sOffA1, Bg1 + bkB);
        asm volatile("cp.async.commit_group;");
    };

    issue_loads(0, 0);
    asm volatile("cp.async.wait_group 0;");
    __syncthreads();

    #pragma unroll 1
    for (int i = 0; i < 48; i++) {
        const int s = i & 1;
        if (i < 47) issue_loads(i + 1, s ^ 1);

        const uint32_t bA = saA + s * STG_A;
        const uint32_t bB = saB + s * STG_A;

        #pragma unroll
        for (int kt = 0; kt < 2; kt++) {
            uint32_t af[2][4], bf[4][4];
            #pragma unroll
            for (int mt = 0; mt < 2; mt++)
                ldsm4(af[mt], bA + rowA[mt] + kt * 32);
            #pragma unroll
            for (int nt = 0; nt < 4; nt++)
                ldsm4(bf[nt], bB + rowB[nt] + kt * 32);
            #pragma unroll
            for (int mt = 0; mt < 2; mt++)
                #pragma unroll
                for (int nt = 0; nt < 4; nt++) {
                    mma16816(acc[mt][nt * 2 + 0], af[mt], bf[nt][0], bf[nt][2]);
                    mma16816(acc[mt][nt * 2 + 1], af[mt], bf[nt][1], bf[nt][3]);
                }
        }

        if (i < 47) {
            asm volatile("cp.async.wait_group 0;");
            __syncthreads();
        }
    }

    const int erow = lane >> 2, ecol = (lane & 3) * 2;
    #pragma unroll
    for (int mt = 0; mt < 2; mt++) {
        float* o0 = out + (size_t)(bm * 128 + wm + mt * 16 + erow) * DIM
                        + bn * 128 + wn + ecol;
        float* o1 = o0 + 8 * DIM;
        #pragma unroll
        for (int j = 0; j < 8; j++) {
            *reinterpret_cast<float2*>(o0 + j * 8) =
                make_float2(acc[mt][j][0], acc[mt][j][1]);
            *reinterpret_cast<float2*>(o1 + j * 8) =
                make_float2(acc[mt][j][2], acc[mt][j][3]);
        }
    }
}

// ---------------------------------------------------------------------------
// kernel_launch: inputs (metadata order): x, weight, row, col, vals
// ---------------------------------------------------------------------------
extern "C" void kernel_launch(void* const* d_in, const int* in_sizes, int n_in,
                              void* d_out, int out_size) {
    const float* x      = (const float*)d_in[0];
    const float* weight = (const float*)d_in[1];
    const void*  row    = d_in[2];
    const void*  col    = d_in[3];
    const float* vals   = (const float*)d_in[4];
    float* out = (float*)d_out;

    (void)in_sizes; (void)n_in; (void)out_size;

    // CSR build
    init_kernel<<<N_NODES / (256 * 4), 256>>>();
    detect_kernel<<<128, 256>>>((const unsigned int*)row);
    hist_kernel<<<N_EDGES / 256, 256>>>(row);
    scan1_kernel<<<256, 256>>>();
    scan2_kernel<<<1, 256>>>();
    scan3_kernel<<<256, 256>>>();
    reorder_kernel<<<N_EDGES / 256, 256>>>(row, col, vals);

    // W split (independent)
    split_W_kernel<<<256, 256>>>(weight);

    // gather SpMM -> g_Ybf (bf16 hi/lo, fused split)
    spmm_kernel<<<N_NODES / 8, 256>>>(x);

    // out = Y2 @ W2^T on tensor cores (mma.sync bf16, 3-term split)
    dim3 grid(4, 512);
    gemm_mma_kernel<<<grid, 256>>>(out);
}

// round 15
// speedup vs baseline: 2.8822x; 1.0113x over previous
#include <cuda_runtime.h>
#include <cuda_bf16.h>
#include <cstdint>

#define N_NODES 65536
#define N_EDGES 524288
#define DIM     512
#define K2      1024   // [hi | lo] split K stride

// ---------------------------------------------------------------------------
// Static device scratch (no allocs allowed)
// ---------------------------------------------------------------------------
__device__ __nv_bfloat16 g_Ybf[(size_t)N_NODES * K2];    // [Yhi | Ylo] bf16
__device__ __nv_bfloat16 g_Wbf[(size_t)DIM * K2];        // [Whi | Wlo] bf16
__device__ unsigned int  g_or_hi;
__device__ int           g_cnt   [N_NODES];
__device__ int           g_start [N_NODES];
__device__ int           g_cursor[N_NODES];
__device__ int           g_blk   [256];
__device__ uint2         g_edges [N_EDGES];              // (col, val-bits) CSR order

// ---------------------------------------------------------------------------
// Kernel 0: zero row counters + dtype-detect accumulator
// ---------------------------------------------------------------------------
__global__ void __launch_bounds__(256) init_kernel() {
    int i = blockIdx.x * blockDim.x + threadIdx.x;
    #pragma unroll
    for (int j = 0; j < 4; j++) g_cnt[i * 4 + j] = 0;
    if (i == 0) g_or_hi = 0u;
}

// ---------------------------------------------------------------------------
// Kernel 1: detect int32 vs int64 indices (OR of odd 32-bit words == 0 => int64)
// ---------------------------------------------------------------------------
__global__ void __launch_bounds__(256) detect_kernel(const unsigned int* __restrict__ rowu) {
    unsigned int v = 0;
    for (int i = blockIdx.x * blockDim.x + threadIdx.x; i < N_EDGES / 2;
         i += gridDim.x * blockDim.x)
        v |= rowu[2 * i + 1];
    #pragma unroll
    for (int s = 16; s > 0; s >>= 1) v |= __shfl_xor_sync(0xFFFFFFFFu, v, s);
    if ((threadIdx.x & 31) == 0 && v) atomicOr(&g_or_hi, v);
}

__device__ __forceinline__ int load_idx(const void* p, int e, bool is64) {
    return is64 ? (int)reinterpret_cast<const long long*>(p)[e]
                : reinterpret_cast<const int*>(p)[e];
}

// ---------------------------------------------------------------------------
// Kernel 2: histogram of row indices
// ---------------------------------------------------------------------------
__global__ void __launch_bounds__(256) hist_kernel(const void* __restrict__ rowp) {
    const bool is64 = (g_or_hi == 0u);
    int e = blockIdx.x * blockDim.x + threadIdx.x;
    atomicAdd(&g_cnt[load_idx(rowp, e, is64)], 1);
}

// ---------------------------------------------------------------------------
// Kernels 3a-3c: exclusive scan of g_cnt (65536) -> g_start, g_cursor
// ---------------------------------------------------------------------------
__global__ void __launch_bounds__(256) scan1_kernel() {   // per-block sums
    __shared__ int sh[256];
    int v = g_cnt[blockIdx.x * 256 + threadIdx.x];
    sh[threadIdx.x] = v;
    __syncthreads();
    for (int s = 128; s > 0; s >>= 1) {
        if (threadIdx.x < s) sh[threadIdx.x] += sh[threadIdx.x + s];
        __syncthreads();
    }
    if (threadIdx.x == 0) g_blk[blockIdx.x] = sh[0];
}
__global__ void __launch_bounds__(256) scan2_kernel() {   // scan of 256 block sums
    __shared__ int sh[256];
    int v = g_blk[threadIdx.x];
    sh[threadIdx.x] = v;
    __syncthreads();
    for (int d = 1; d < 256; d <<= 1) {
        int t = (threadIdx.x >= d) ? sh[threadIdx.x - d] : 0;
        __syncthreads();
        sh[threadIdx.x] += t;
        __syncthreads();
    }
    g_blk[threadIdx.x] = sh[threadIdx.x] - v;   // exclusive
}
__global__ void __launch_bounds__(256) scan3_kernel() {   // local scan + offset
    __shared__ int sh[256];
    int i = blockIdx.x * 256 + threadIdx.x;
    int v = g_cnt[i];
    sh[threadIdx.x] = v;
    __syncthreads();
    for (int d = 1; d < 256; d <<= 1) {
        int t = (threadIdx.x >= d) ? sh[threadIdx.x - d] : 0;
        __syncthreads();
        sh[threadIdx.x] += t;
        __syncthreads();
    }
    int st = g_blk[blockIdx.x] + sh[threadIdx.x] - v;     // exclusive
    g_start[i]  = st;
    g_cursor[i] = st;
}

// ---------------------------------------------------------------------------
// Kernel 4: reorder edges into CSR order (packed col + val bits)
// ---------------------------------------------------------------------------
__global__ void __launch_bounds__(256) reorder_kernel(const void* __restrict__ rowp,
                                                      const void* __restrict__ colp,
                                                      const float* __restrict__ vals) {
    const bool is64 = (g_or_hi == 0u);
    int e = blockIdx.x * blockDim.x + threadIdx.x;
    int r = load_idx(rowp, e, is64);
    int c = load_idx(colp, e, is64);
    int pos = atomicAdd(&g_cursor[r], 1);
    g_edges[pos] = make_uint2((unsigned)c, __float_as_uint(vals[e]));
}

// ---------------------------------------------------------------------------
// Kernel 5: gather SpMM. One warp per row, 4-edge unroll (16 LDG.128 in
// flight per lane group). Epilogue writes bf16 [hi|lo] split directly.
// ---------------------------------------------------------------------------
__global__ void __launch_bounds__(256) spmm_kernel(const float* __restrict__ x) {
    const int row  = blockIdx.x * 8 + (threadIdx.x >> 5);
    const int lane = threadIdx.x & 31;
    const int s = g_start[row];
    const int e = s + g_cnt[row];

    float4 acc[4];
    #pragma unroll
    for (int j = 0; j < 4; j++) acc[j] = make_float4(0.f, 0.f, 0.f, 0.f);

    int i = s;
    // 4-edge unroll
    for (; i + 3 < e; i += 4) {
        uint2 p[4];
        #pragma unroll
        for (int q = 0; q < 4; q++) p[q] = g_edges[i + q];
        float4 t[4][4];
        #pragma unroll
        for (int q = 0; q < 4; q++) {
            const float4* xs = reinterpret_cast<const float4*>(x + (size_t)p[q].x * DIM);
            #pragma unroll
            for (int j = 0; j < 4; j++) t[q][j] = xs[lane + 32 * j];
        }
        #pragma unroll
        for (int q = 0; q < 4; q++) {
            float v = __uint_as_float(p[q].y);
            #pragma unroll
            for (int j = 0; j < 4; j++) {
                acc[j].x += v * t[q][j].x;
                acc[j].y += v * t[q][j].y;
                acc[j].z += v * t[q][j].z;
                acc[j].w += v * t[q][j].w;
            }
        }
    }
    // 2-edge remainder
    for (; i + 1 < e; i += 2) {
        uint2 p0 = g_edges[i], p1 = g_edges[i + 1];
        const float4* x0 = reinterpret_cast<const float4*>(x + (size_t)p0.x * DIM);
        const float4* x1 = reinterpret_cast<const float4*>(x + (size_t)p1.x * DIM);
        float v0 = __uint_as_float(p0.y), v1 = __uint_as_float(p1.y);
        float4 t0[4], t1[4];
        #pragma unroll
        for (int j = 0; j < 4; j++) { t0[j] = x0[lane + 32 * j]; t1[j] = x1[lane + 32 * j]; }
        #pragma unroll
        for (int j = 0; j < 4; j++) {
            acc[j].x += v0 * t0[j].x + v1 * t1[j].x;
            acc[j].y += v0 * t0[j].y + v1 * t1[j].y;
            acc[j].z += v0 * t0[j].z + v1 * t1[j].z;
            acc[j].w += v0 * t0[j].w + v1 * t1[j].w;
        }
    }
    if (i < e) {
        uint2 p = g_edges[i];
        const float4* xs = reinterpret_cast<const float4*>(x + (size_t)p.x * DIM);
        float v = __uint_as_float(p.y);
        #pragma unroll
        for (int j = 0; j < 4; j++) {
            float4 t = xs[lane + 32 * j];
            acc[j].x += v * t.x; acc[j].y += v * t.y;
            acc[j].z += v * t.z; acc[j].w += v * t.w;
        }
    }

    // epilogue: split fp32 -> bf16 hi/lo, write both halves
    __nv_bfloat16* dst = g_Ybf + (size_t)row * K2;
    #pragma unroll
    for (int j = 0; j < 4; j++) {
        int c4 = lane + 32 * j;
        float f[4] = {acc[j].x, acc[j].y, acc[j].z, acc[j].w};
        unsigned short h[4], l[4];
        #pragma unroll
        for (int k = 0; k < 4; k++) {
            __nv_bfloat16 hb = __float2bfloat16_rn(f[k]);
            __nv_bfloat16 lb = __float2bfloat16_rn(f[k] - __bfloat162float(hb));
            h[k] = __bfloat16_as_ushort(hb);
            l[k] = __bfloat16_as_ushort(lb);
        }
        uint2 hp, lp;
        hp.x = (uint32_t)h[0] | ((uint32_t)h[1] << 16);
        hp.y = (uint32_t)h[2] | ((uint32_t)h[3] << 16);
        lp.x = (uint32_t)l[0] | ((uint32_t)l[1] << 16);
        lp.y = (uint32_t)l[2] | ((uint32_t)l[3] << 16);
        *reinterpret_cast<uint2*>(dst + 4 * c4)       = hp;
        *reinterpret_cast<uint2*>(dst + 512 + 4 * c4) = lp;
    }
}

// ---------------------------------------------------------------------------
// Kernel 6: split W fp32 -> [hi | lo] bf16
// ---------------------------------------------------------------------------
__global__ void __launch_bounds__(256) split_W_kernel(const float* __restrict__ W) {
    const size_t n4 = (size_t)DIM * (DIM / 4);
    for (size_t i = (size_t)blockIdx.x * blockDim.x + threadIdx.x; i < n4;
         i += (size_t)gridDim.x * blockDim.x) {
        float4 v = reinterpret_cast<const float4*>(W)[i];
        size_t e = i * 4;
        size_t row = e >> 9;
        int col = (int)(e & 511);
        float f[4] = {v.x, v.y, v.z, v.w};
        unsigned short h[4], l[4];
        #pragma unroll
        for (int k = 0; k < 4; k++) {
            __nv_bfloat16 hb = __float2bfloat16_rn(f[k]);
            __nv_bfloat16 lb = __float2bfloat16_rn(f[k] - __bfloat162float(hb));
            h[k] = __bfloat16_as_ushort(hb);
            l[k] = __bfloat16_as_ushort(lb);
        }
        uint2 hp, lp;
        hp.x = (uint32_t)h[0] | ((uint32_t)h[1] << 16);
        hp.y = (uint32_t)h[2] | ((uint32_t)h[3] << 16);
        lp.x = (uint32_t)l[0] | ((uint32_t)l[1] << 16);
        lp.y = (uint32_t)l[2] | ((uint32_t)l[3] << 16);
        *reinterpret_cast<uint2*>(g_Wbf + row * K2 + col)       = hp;
        *reinterpret_cast<uint2*>(g_Wbf + row * K2 + 512 + col) = lp;
    }
}

// ---------------------------------------------------------------------------
// Kernel 7: mma.sync bf16 GEMM   out[65536,512] = Y2 @ W2^T  (3-term split)
// CTA tile 128x128, BK=32, 8 warps (4x2) each 32x64.
// 3-stage cp.async pipeline, ONE __syncthreads per iteration.
// ---------------------------------------------------------------------------
#define RSTR  80               // padded smem row stride (conflict-free ldmatrix)
#define NSTAGE 3

__device__ __forceinline__ uint32_t smem_u32(const void* p) {
    uint32_t a;
    asm("{ .reg .u64 t; cvta.to.shared.u64 t, %1; cvt.u32.u64 %0, t; }"
        : "=r"(a) : "l"(p));
    return a;
}
__device__ __forceinline__ void cp16(uint32_t smem, const void* gmem) {
    asm volatile("cp.async.cg.shared.global [%0], [%1], 16;"
                 :: "r"(smem), "l"(gmem));
}
__device__ __forceinline__ void ldsm4(uint32_t* r, uint32_t addr) {
    asm volatile("ldmatrix.sync.aligned.m8n8.x4.shared.b16 {%0,%1,%2,%3}, [%4];"
                 : "=r"(r[0]), "=r"(r[1]), "=r"(r[2]), "=r"(r[3]) : "r"(addr));
}
__device__ __forceinline__ void mma16816(float* d, const uint32_t* a,
                                         uint32_t b0, uint32_t b1) {
    asm volatile(
        "mma.sync.aligned.m16n8k16.row.col.f32.bf16.bf16.f32 "
        "{%0,%1,%2,%3}, {%4,%5,%6,%7}, {%8,%9}, {%0,%1,%2,%3};"
        : "+f"(d[0]), "+f"(d[1]), "+f"(d[2]), "+f"(d[3])
        : "r"(a[0]), "r"(a[1]), "r"(a[2]), "r"(a[3]), "r"(b0), "r"(b1));
}

__global__ void __launch_bounds__(256) gemm_mma_kernel(float* __restrict__ out) {
    __shared__ char sA[NSTAGE][128 * RSTR];
    __shared__ char sB[NSTAGE][128 * RSTR];

    const int tid  = threadIdx.x;
    const int wid  = tid >> 5;
    const int lane = tid & 31;
    const int bn   = blockIdx.x;   // 0..3  (N tiles of 128)
    const int bm   = blockIdx.y;   // 0..511 (M tiles of 128)

    const int wm = (wid >> 1) * 32;
    const int wn = (wid & 1) * 64;

    int r0 = tid >> 2, c0 = (tid & 3) * 16;
    int r1 = (tid + 256) >> 2, c1 = c0;
    const char* Ag0 = (const char*)(g_Ybf + (size_t)(bm * 128 + r0) * K2) + c0;
    const char* Ag1 = (const char*)(g_Ybf + (size_t)(bm * 128 + r1) * K2) + c1;
    const char* Bg0 = (const char*)(g_Wbf + (size_t)(bn * 128 + r0) * K2) + c0;
    const char* Bg1 = (const char*)(g_Wbf + (size_t)(bn * 128 + r1) * K2) + c1;
    const int sOff0 = r0 * RSTR + c0, sOff1 = r1 * RSTR + c1;

    const uint32_t saA = smem_u32(sA[0]);
    const uint32_t saB = smem_u32(sB[0]);
    const uint32_t STG = 128 * RSTR;

    const int lrow = lane & 15;
    const int lhalf = ((lane >> 4) & 1) * 16;
    uint32_t rowA[2], rowB[4];
    #pragma unroll
    for (int mt = 0; mt < 2; mt++)
        rowA[mt] = (uint32_t)((wm + mt * 16 + lrow) * RSTR + lhalf);
    #pragma unroll
    for (int nt = 0; nt < 4; nt++)
        rowB[nt] = (uint32_t)((wn + nt * 16 + lrow) * RSTR + lhalf);

    float acc[2][8][4];
    #pragma unroll
    for (int mt = 0; mt < 2; mt++)
        #pragma unroll
        for (int j = 0; j < 8; j++)
            #pragma unroll
            for (int q = 0; q < 4; q++) acc[mt][j][q] = 0.f;

    // chunk i (0..47): p = i>>4 selects split term, c = i&15 -> k offset
    auto issue_loads = [&](int i, int s) {
        const int p = i >> 4, c = i & 15;
        const int akB = (((p == 2) ? 512 : 0) + c * 32) * 2;
        const int bkB = (((p == 1) ? 512 : 0) + c * 32) * 2;
        uint32_t dA = saA + s * STG;
        uint32_t dB = saB + s * STG;
        cp16(dA + sOff0, Ag0 + akB);
        cp16(dA + sOff1, Ag1 + akB);
        cp16(dB + sOff0, Bg0 + bkB);
        cp16(dB + sOff1, Bg1 + bkB);
        asm volatile("cp.async.commit_group;");
    };

    // prologue: 2 stages in flight
    issue_loads(0, 0);
    issue_loads(1, 1);

    #pragma unroll 1
    for (int i = 0; i < 48; i++) {
        const int s = i % NSTAGE;
        // wait for stage i's group (outstanding: {i, i+1} except tail)
        if (i < 47) asm volatile("cp.async.wait_group 1;");
        else        asm volatile("cp.async.wait_group 0;");
        __syncthreads();
        // safe: buffer (i+2)%3 was last read in compute(i-1), finished before
        // the barrier above
        if (i + 2 < 48) issue_loads(i + 2, (i + 2) % NSTAGE);

        const uint32_t bA = saA + s * STG;
        const uint32_t bB = saB + s * STG;

        #pragma unroll
        for (int kt = 0; kt < 2; kt++) {
            uint32_t af[2][4], bf[4][4];
            #pragma unroll
            for (int mt = 0; mt < 2; mt++)
                ldsm4(af[mt], bA + rowA[mt] + kt * 32);
            #pragma unroll
            for (int nt = 0; nt < 4; nt++)
                ldsm4(bf[nt], bB + rowB[nt] + kt * 32);
            #pragma unroll
            for (int mt = 0; mt < 2; mt++)
                #pragma unroll
                for (int nt = 0; nt < 4; nt++) {
                    mma16816(acc[mt][nt * 2 + 0], af[mt], bf[nt][0], bf[nt][2]);
                    mma16816(acc[mt][nt * 2 + 1], af[mt], bf[nt][1], bf[nt][3]);
                }
        }
    }

    const int erow = lane >> 2, ecol = (lane & 3) * 2;
    #pragma unroll
    for (int mt = 0; mt < 2; mt++) {
        float* o0 = out + (size_t)(bm * 128 + wm + mt * 16 + erow) * DIM
                        + bn * 128 + wn + ecol;
        float* o1 = o0 + 8 * DIM;
        #pragma unroll
        for (int j = 0; j < 8; j++) {
            *reinterpret_cast<float2*>(o0 + j * 8) =
                make_float2(acc[mt][j][0], acc[mt][j][1]);
            *reinterpret_cast<float2*>(o1 + j * 8) =
                make_float2(acc[mt][j][2], acc[mt][j][3]);
        }
    }
}

// ---------------------------------------------------------------------------
// kernel_launch: inputs (metadata order): x, weight, row, col, vals
// ---------------------------------------------------------------------------
extern "C" void kernel_launch(void* const* d_in, const int* in_sizes, int n_in,
                              void* d_out, int out_size) {
    const float* x      = (const float*)d_in[0];
    const float* weight = (const float*)d_in[1];
    const void*  row    = d_in[2];
    const void*  col    = d_in[3];
    const float* vals   = (const float*)d_in[4];
    float* out = (float*)d_out;

    (void)in_sizes; (void)n_in; (void)out_size;

    // CSR build
    init_kernel<<<N_NODES / (256 * 4), 256>>>();
    detect_kernel<<<128, 256>>>((const unsigned int*)row);
    hist_kernel<<<N_EDGES / 256, 256>>>(row);
    scan1_kernel<<<256, 256>>>();
    scan2_kernel<<<1, 256>>>();
    scan3_kernel<<<256, 256>>>();
    reorder_kernel<<<N_EDGES / 256, 256>>>(row, col, vals);

    // W split (independent)
    split_W_kernel<<<256, 256>>>(weight);

    // gather SpMM -> g_Ybf (bf16 hi/lo, fused split)
    spmm_kernel<<<N_NODES / 8, 256>>>(x);

    // out = Y2 @ W2^T on tensor cores (mma.sync bf16, 3-term split)
    dim3 grid(4, 512);
    gemm_mma_kernel<<<grid, 256>>>(out);
}

// round 16
// speedup vs baseline: 3.6923x; 1.2811x over previous
#include <cuda_runtime.h>
#include <cuda_fp16.h>
#include <cstdint>

#define N_NODES 65536
#define N_EDGES 524288
#define DIM     512
#define K2      1024   // [hi | lo] split K stride for Y

// ---------------------------------------------------------------------------
// Static device scratch (no allocs allowed)
// ---------------------------------------------------------------------------
__device__ __half        g_Yhf[(size_t)N_NODES * K2];    // [Yhi | Ylo] fp16
__device__ __half        g_Whf[(size_t)DIM * DIM];       // W fp16 (rounded)
__device__ unsigned int  g_or_hi;
__device__ int           g_cnt   [N_NODES];
__device__ int           g_start [N_NODES];
__device__ int           g_cursor[N_NODES];
__device__ int           g_blk   [256];
__device__ uint2         g_edges [N_EDGES];              // (col, val-bits) CSR order

// ---------------------------------------------------------------------------
// Kernel 0: zero row counters + dtype-detect accumulator
// ---------------------------------------------------------------------------
__global__ void __launch_bounds__(256) init_kernel() {
    int i = blockIdx.x * blockDim.x + threadIdx.x;
    #pragma unroll
    for (int j = 0; j < 4; j++) g_cnt[i * 4 + j] = 0;
    if (i == 0) g_or_hi = 0u;
}

// ---------------------------------------------------------------------------
// Kernel 1: detect int32 vs int64 indices (OR of odd 32-bit words == 0 => int64)
// ---------------------------------------------------------------------------
__global__ void __launch_bounds__(256) detect_kernel(const unsigned int* __restrict__ rowu) {
    unsigned int v = 0;
    for (int i = blockIdx.x * blockDim.x + threadIdx.x; i < N_EDGES / 2;
         i += gridDim.x * blockDim.x)
        v |= rowu[2 * i + 1];
    #pragma unroll
    for (int s = 16; s > 0; s >>= 1) v |= __shfl_xor_sync(0xFFFFFFFFu, v, s);
    if ((threadIdx.x & 31) == 0 && v) atomicOr(&g_or_hi, v);
}

__device__ __forceinline__ int load_idx(const void* p, int e, bool is64) {
    return is64 ? (int)reinterpret_cast<const long long*>(p)[e]
                : reinterpret_cast<const int*>(p)[e];
}

// ---------------------------------------------------------------------------
// Kernel 2: histogram of row indices
// ---------------------------------------------------------------------------
__global__ void __launch_bounds__(256) hist_kernel(const void* __restrict__ rowp) {
    const bool is64 = (g_or_hi == 0u);
    int e = blockIdx.x * blockDim.x + threadIdx.x;
    atomicAdd(&g_cnt[load_idx(rowp, e, is64)], 1);
}

// ---------------------------------------------------------------------------
// Kernels 3a-3c: exclusive scan of g_cnt (65536) -> g_start, g_cursor
// ---------------------------------------------------------------------------
__global__ void __launch_bounds__(256) scan1_kernel() {
    __shared__ int sh[256];
    int v = g_cnt[blockIdx.x * 256 + threadIdx.x];
    sh[threadIdx.x] = v;
    __syncthreads();
    for (int s = 128; s > 0; s >>= 1) {
        if (threadIdx.x < s) sh[threadIdx.x] += sh[threadIdx.x + s];
        __syncthreads();
    }
    if (threadIdx.x == 0) g_blk[blockIdx.x] = sh[0];
}
__global__ void __launch_bounds__(256) scan2_kernel() {
    __shared__ int sh[256];
    int v = g_blk[threadIdx.x];
    sh[threadIdx.x] = v;
    __syncthreads();
    for (int d = 1; d < 256; d <<= 1) {
        int t = (threadIdx.x >= d) ? sh[threadIdx.x - d] : 0;
        __syncthreads();
        sh[threadIdx.x] += t;
        __syncthreads();
    }
    g_blk[threadIdx.x] = sh[threadIdx.x] - v;   // exclusive
}
__global__ void __launch_bounds__(256) scan3_kernel() {
    __shared__ int sh[256];
    int i = blockIdx.x * 256 + threadIdx.x;
    int v = g_cnt[i];
    sh[threadIdx.x] = v;
    __syncthreads();
    for (int d = 1; d < 256; d <<= 1) {
        int t = (threadIdx.x >= d) ? sh[threadIdx.x - d] : 0;
        __syncthreads();
        sh[threadIdx.x] += t;
        __syncthreads();
    }
    int st = g_blk[blockIdx.x] + sh[threadIdx.x] - v;     // exclusive
    g_start[i]  = st;
    g_cursor[i] = st;
}

// ---------------------------------------------------------------------------
// Kernel 4: reorder edges into CSR order (packed col + val bits)
// ---------------------------------------------------------------------------
__global__ void __launch_bounds__(256) reorder_kernel(const void* __restrict__ rowp,
                                                      const void* __restrict__ colp,
                                                      const float* __restrict__ vals) {
    const bool is64 = (g_or_hi == 0u);
    int e = blockIdx.x * blockDim.x + threadIdx.x;
    int r = load_idx(rowp, e, is64);
    int c = load_idx(colp, e, is64);
    int pos = atomicAdd(&g_cursor[r], 1);
    g_edges[pos] = make_uint2((unsigned)c, __float_as_uint(vals[e]));
}

// ---------------------------------------------------------------------------
// Kernel 5: gather SpMM. One warp per row, 4-edge unroll.
// Epilogue writes fp16 [hi|lo] split directly into g_Yhf.
// ---------------------------------------------------------------------------
__global__ void __launch_bounds__(256) spmm_kernel(const float* __restrict__ x) {
    const int row  = blockIdx.x * 8 + (threadIdx.x >> 5);
    const int lane = threadIdx.x & 31;
    const int s = g_start[row];
    const int e = s + g_cnt[row];

    float4 acc[4];
    #pragma unroll
    for (int j = 0; j < 4; j++) acc[j] = make_float4(0.f, 0.f, 0.f, 0.f);

    int i = s;
    for (; i + 3 < e; i += 4) {
        uint2 p[4];
        #pragma unroll
        for (int q = 0; q < 4; q++) p[q] = g_edges[i + q];
        float4 t[4][4];
        #pragma unroll
        for (int q = 0; q < 4; q++) {
            const float4* xs = reinterpret_cast<const float4*>(x + (size_t)p[q].x * DIM);
            #pragma unroll
            for (int j = 0; j < 4; j++) t[q][j] = xs[lane + 32 * j];
        }
        #pragma unroll
        for (int q = 0; q < 4; q++) {
            float v = __uint_as_float(p[q].y);
            #pragma unroll
            for (int j = 0; j < 4; j++) {
                acc[j].x += v * t[q][j].x;
                acc[j].y += v * t[q][j].y;
                acc[j].z += v * t[q][j].z;
                acc[j].w += v * t[q][j].w;
            }
        }
    }
    for (; i + 1 < e; i += 2) {
        uint2 p0 = g_edges[i], p1 = g_edges[i + 1];
        const float4* x0 = reinterpret_cast<const float4*>(x + (size_t)p0.x * DIM);
        const float4* x1 = reinterpret_cast<const float4*>(x + (size_t)p1.x * DIM);
        float v0 = __uint_as_float(p0.y), v1 = __uint_as_float(p1.y);
        float4 t0[4], t1[4];
        #pragma unroll
        for (int j = 0; j < 4; j++) { t0[j] = x0[lane + 32 * j]; t1[j] = x1[lane + 32 * j]; }
        #pragma unroll
        for (int j = 0; j < 4; j++) {
            acc[j].x += v0 * t0[j].x + v1 * t1[j].x;
            acc[j].y += v0 * t0[j].y + v1 * t1[j].y;
            acc[j].z += v0 * t0[j].z + v1 * t1[j].z;
            acc[j].w += v0 * t0[j].w + v1 * t1[j].w;
        }
    }
    if (i < e) {
        uint2 p = g_edges[i];
        const float4* xs = reinterpret_cast<const float4*>(x + (size_t)p.x * DIM);
        float v = __uint_as_float(p.y);
        #pragma unroll
        for (int j = 0; j < 4; j++) {
            float4 t = xs[lane + 32 * j];
            acc[j].x += v * t.x; acc[j].y += v * t.y;
            acc[j].z += v * t.z; acc[j].w += v * t.w;
        }
    }

    // epilogue: split fp32 -> fp16 hi/lo, write both halves
    __half* dst = g_Yhf + (size_t)row * K2;
    #pragma unroll
    for (int j = 0; j < 4; j++) {
        int c4 = lane + 32 * j;
        float f[4] = {acc[j].x, acc[j].y, acc[j].z, acc[j].w};
        unsigned short h[4], l[4];
        #pragma unroll
        for (int k = 0; k < 4; k++) {
            __half hb = __float2half_rn(f[k]);
            __half lb = __float2half_rn(f[k] - __half2float(hb));
            h[k] = __half_as_ushort(hb);
            l[k] = __half_as_ushort(lb);
        }
        uint2 hp, lp;
        hp.x = (uint32_t)h[0] | ((uint32_t)h[1] << 16);
        hp.y = (uint32_t)h[2] | ((uint32_t)h[3] << 16);
        lp.x = (uint32_t)l[0] | ((uint32_t)l[1] << 16);
        lp.y = (uint32_t)l[2] | ((uint32_t)l[3] << 16);
        *reinterpret_cast<uint2*>(dst + 4 * c4)       = hp;
        *reinterpret_cast<uint2*>(dst + 512 + 4 * c4) = lp;
    }
}

// ---------------------------------------------------------------------------
// Kernel 6: round W fp32 -> fp16
// ---------------------------------------------------------------------------
__global__ void __launch_bounds__(256) cvt_W_kernel(const float* __restrict__ W) {
    const size_t n4 = (size_t)DIM * (DIM / 4);
    for (size_t i = (size_t)blockIdx.x * blockDim.x + threadIdx.x; i < n4;
         i += (size_t)gridDim.x * blockDim.x) {
        float4 v = reinterpret_cast<const float4*>(W)[i];
        unsigned short h[4];
        h[0] = __half_as_ushort(__float2half_rn(v.x));
        h[1] = __half_as_ushort(__float2half_rn(v.y));
        h[2] = __half_as_ushort(__float2half_rn(v.z));
        h[3] = __half_as_ushort(__float2half_rn(v.w));
        uint2 hp;
        hp.x = (uint32_t)h[0] | ((uint32_t)h[1] << 16);
        hp.y = (uint32_t)h[2] | ((uint32_t)h[3] << 16);
        *reinterpret_cast<uint2*>(g_Whf + i * 4) = hp;
    }
}

// ---------------------------------------------------------------------------
// Kernel 7: mma.sync fp16 GEMM   out[65536,512] = (Yhi+Ylo) @ W16^T
// CTA tile 128x128, BK=32, 8 warps (4x2) each 32x64.
// 3-stage cp.async pipeline, one __syncthreads per iteration.
// K' = 2*512 = 1024 -> 32 chunks of 32 (both halves hit the SAME B chunk).
// ---------------------------------------------------------------------------
#define RSTR  80               // padded smem row stride (conflict-free ldmatrix)
#define NSTAGE 3

__device__ __forceinline__ uint32_t smem_u32(const void* p) {
    uint32_t a;
    asm("{ .reg .u64 t; cvta.to.shared.u64 t, %1; cvt.u32.u64 %0, t; }"
        : "=r"(a) : "l"(p));
    return a;
}
__device__ __forceinline__ void cp16(uint32_t smem, const void* gmem) {
    asm volatile("cp.async.cg.shared.global [%0], [%1], 16;"
                 :: "r"(smem), "l"(gmem));
}
__device__ __forceinline__ void ldsm4(uint32_t* r, uint32_t addr) {
    asm volatile("ldmatrix.sync.aligned.m8n8.x4.shared.b16 {%0,%1,%2,%3}, [%4];"
                 : "=r"(r[0]), "=r"(r[1]), "=r"(r[2]), "=r"(r[3]) : "r"(addr));
}
__device__ __forceinline__ void mma16816(float* d, const uint32_t* a,
                                         uint32_t b0, uint32_t b1) {
    asm volatile(
        "mma.sync.aligned.m16n8k16.row.col.f32.f16.f16.f32 "
        "{%0,%1,%2,%3}, {%4,%5,%6,%7}, {%8,%9}, {%0,%1,%2,%3};"
        : "+f"(d[0]), "+f"(d[1]), "+f"(d[2]), "+f"(d[3])
        : "r"(a[0]), "r"(a[1]), "r"(a[2]), "r"(a[3]), "r"(b0), "r"(b1));
}

__global__ void __launch_bounds__(256) gemm_mma_kernel(float* __restrict__ out) {
    __shared__ char sA[NSTAGE][128 * RSTR];
    __shared__ char sB[NSTAGE][128 * RSTR];

    const int tid  = threadIdx.x;
    const int wid  = tid >> 5;
    const int lane = tid & 31;
    const int bn   = blockIdx.x;   // 0..3  (N tiles of 128)
    const int bm   = blockIdx.y;   // 0..511 (M tiles of 128)

    const int wm = (wid >> 1) * 32;
    const int wn = (wid & 1) * 64;

    int r0 = tid >> 2, c0 = (tid & 3) * 16;
    int r1 = (tid + 256) >> 2, c1 = c0;
    // A rows: stride K2 fp16; B rows: stride DIM fp16
    const char* Ag0 = (const char*)(g_Yhf + (size_t)(bm * 128 + r0) * K2) + c0;
    const char* Ag1 = (const char*)(g_Yhf + (size_t)(bm * 128 + r1) * K2) + c1;
    const char* Bg0 = (const char*)(g_Whf + (size_t)(bn * 128 + r0) * DIM) + c0;
    const char* Bg1 = (const char*)(g_Whf + (size_t)(bn * 128 + r1) * DIM) + c1;
    const int sOff0 = r0 * RSTR + c0, sOff1 = r1 * RSTR + c1;

    const uint32_t saA = smem_u32(sA[0]);
    const uint32_t saB = smem_u32(sB[0]);
    const uint32_t STG = 128 * RSTR;

    const int lrow = lane & 15;
    const int lhalf = ((lane >> 4) & 1) * 16;
    uint32_t rowA[2], rowB[4];
    #pragma unroll
    for (int mt = 0; mt < 2; mt++)
        rowA[mt] = (uint32_t)((wm + mt * 16 + lrow) * RSTR + lhalf);
    #pragma unroll
    for (int nt = 0; nt < 4; nt++)
        rowB[nt] = (uint32_t)((wn + nt * 16 + lrow) * RSTR + lhalf);

    float acc[2][8][4];
    #pragma unroll
    for (int mt = 0; mt < 2; mt++)
        #pragma unroll
        for (int j = 0; j < 8; j++)
            #pragma unroll
            for (int q = 0; q < 4; q++) acc[mt][j][q] = 0.f;

    // chunk i (0..31): half = i>>4 (A hi/lo), c = i&15 -> k offset.
    // B offset depends only on c (same B data for both halves -> L2-hot).
    auto issue_loads = [&](int i, int s) {
        const int half = i >> 4, c = i & 15;
        const int akB = (half * 512 + c * 32) * 2;   // bytes into A row
        const int bkB = (c * 32) * 2;                // bytes into B row
        uint32_t dA = saA + s * STG;
        uint32_t dB = saB + s * STG;
        cp16(dA + sOff0, Ag0 + akB);
        cp16(dA + sOff1, Ag1 + akB);
        cp16(dB + sOff0, Bg0 + bkB);
        cp16(dB + sOff1, Bg1 + bkB);
        asm volatile("cp.async.commit_group;");
    };

    issue_loads(0, 0);
    issue_loads(1, 1);

    #pragma unroll 1
    for (int i = 0; i < 32; i++) {
        const int s = i % NSTAGE;
        if (i < 31) asm volatile("cp.async.wait_group 1;");
        else        asm volatile("cp.async.wait_group 0;");
        __syncthreads();
        if (i + 2 < 32) issue_loads(i + 2, (i + 2) % NSTAGE);

        const uint32_t bA = saA + s * STG;
        const uint32_t bB = saB + s * STG;

        #pragma unroll
        for (int kt = 0; kt < 2; kt++) {
            uint32_t af[2][4], bf[4][4];
            #pragma unroll
            for (int mt = 0; mt < 2; mt++)
                ldsm4(af[mt], bA + rowA[mt] + kt * 32);
            #pragma unroll
            for (int nt = 0; nt < 4; nt++)
                ldsm4(bf[nt], bB + rowB[nt] + kt * 32);
            #pragma unroll
            for (int mt = 0; mt < 2; mt++)
                #pragma unroll
                for (int nt = 0; nt < 4; nt++) {
                    mma16816(acc[mt][nt * 2 + 0], af[mt], bf[nt][0], bf[nt][2]);
                    mma16816(acc[mt][nt * 2 + 1], af[mt], bf[nt][1], bf[nt][3]);
                }
        }
    }

    const int erow = lane >> 2, ecol = (lane & 3) * 2;
    #pragma unroll
    for (int mt = 0; mt < 2; mt++) {
        float* o0 = out + (size_t)(bm * 128 + wm + mt * 16 + erow) * DIM
                        + bn * 128 + wn + ecol;
        float* o1 = o0 + 8 * DIM;
        #pragma unroll
        for (int j = 0; j < 8; j++) {
            *reinterpret_cast<float2*>(o0 + j * 8) =
                make_float2(acc[mt][j][0], acc[mt][j][1]);
            *reinterpret_cast<float2*>(o1 + j * 8) =
                make_float2(acc[mt][j][2], acc[mt][j][3]);
        }
    }
}

// ---------------------------------------------------------------------------
// kernel_launch: inputs (metadata order): x, weight, row, col, vals
// ---------------------------------------------------------------------------
extern "C" void kernel_launch(void* const* d_in, const int* in_sizes, int n_in,
                              void* d_out, int out_size) {
    const float* x      = (const float*)d_in[0];
    const float* weight = (const float*)d_in[1];
    const void*  row    = d_in[2];
    const void*  col    = d_in[3];
    const float* vals   = (const float*)d_in[4];
    float* out = (float*)d_out;

    (void)in_sizes; (void)n_in; (void)out_size;

    // CSR build
    init_kernel<<<N_NODES / (256 * 4), 256>>>();
    detect_kernel<<<128, 256>>>((const unsigned int*)row);
    hist_kernel<<<N_EDGES / 256, 256>>>(row);
    scan1_kernel<<<256, 256>>>();
    scan2_kernel<<<1, 256>>>();
    scan3_kernel<<<256, 256>>>();
    reorder_kernel<<<N_EDGES / 256, 256>>>(row, col, vals);

    // W -> fp16 (independent)
    cvt_W_kernel<<<256, 256>>>(weight);

    // gather SpMM -> g_Yhf (fp16 hi/lo, fused split)
    spmm_kernel<<<N_NODES / 8, 256>>>(x);

    // out = (Yhi+Ylo) @ W16^T on tensor cores (fp16 mma, 2-term split)
    dim3 grid(4, 512);
    gemm_mma_kernel<<<grid, 256>>>(out);
}

// round 17
// speedup vs baseline: 3.8400x; 1.0400x over previous
#include <cuda_runtime.h>
#include <cuda_fp16.h>
#include <cstdint>

#define N_NODES 65536
#define N_EDGES 524288
#define DIM     512
#define K2      1024   // [hi | lo] split K stride for Y

// ---------------------------------------------------------------------------
// Static device scratch (no allocs allowed)
// ---------------------------------------------------------------------------
__device__ __half        g_xhf[(size_t)N_NODES * DIM];   // x rounded to fp16
__device__ __half        g_Yhf[(size_t)N_NODES * K2];    // [Yhi | Ylo] fp16
__device__ __half        g_Whf[(size_t)DIM * DIM];       // W fp16 (rounded)
__device__ unsigned int  g_or_hi;
__device__ int           g_cnt   [N_NODES];
__device__ int           g_start [N_NODES];
__device__ int           g_cursor[N_NODES];
__device__ int           g_blk   [256];
__device__ uint2         g_edges [N_EDGES];              // (col, val-bits) CSR order

// ---------------------------------------------------------------------------
// Kernel 0: zero row counters + dtype-detect accumulator
// ---------------------------------------------------------------------------
__global__ void __launch_bounds__(256) init_kernel() {
    int i = blockIdx.x * blockDim.x + threadIdx.x;
    #pragma unroll
    for (int j = 0; j < 4; j++) g_cnt[i * 4 + j] = 0;
    if (i == 0) g_or_hi = 0u;
}

// ---------------------------------------------------------------------------
// Kernel 1: detect int32 vs int64 indices (OR of odd 32-bit words == 0 => int64)
// ---------------------------------------------------------------------------
__global__ void __launch_bounds__(256) detect_kernel(const unsigned int* __restrict__ rowu) {
    unsigned int v = 0;
    for (int i = blockIdx.x * blockDim.x + threadIdx.x; i < N_EDGES / 2;
         i += gridDim.x * blockDim.x)
        v |= rowu[2 * i + 1];
    #pragma unroll
    for (int s = 16; s > 0; s >>= 1) v |= __shfl_xor_sync(0xFFFFFFFFu, v, s);
    if ((threadIdx.x & 31) == 0 && v) atomicOr(&g_or_hi, v);
}

__device__ __forceinline__ int load_idx(const void* p, int e, bool is64) {
    return is64 ? (int)reinterpret_cast<const long long*>(p)[e]
                : reinterpret_cast<const int*>(p)[e];
}

// ---------------------------------------------------------------------------
// Kernel 2: histogram of row indices
// ---------------------------------------------------------------------------
__global__ void __launch_bounds__(256) hist_kernel(const void* __restrict__ rowp) {
    const bool is64 = (g_or_hi == 0u);
    int e = blockIdx.x * blockDim.x + threadIdx.x;
    atomicAdd(&g_cnt[load_idx(rowp, e, is64)], 1);
}

// ---------------------------------------------------------------------------
// Kernels 3a-3c: exclusive scan of g_cnt (65536) -> g_start, g_cursor
// ---------------------------------------------------------------------------
__global__ void __launch_bounds__(256) scan1_kernel() {
    __shared__ int sh[256];
    int v = g_cnt[blockIdx.x * 256 + threadIdx.x];
    sh[threadIdx.x] = v;
    __syncthreads();
    for (int s = 128; s > 0; s >>= 1) {
        if (threadIdx.x < s) sh[threadIdx.x] += sh[threadIdx.x + s];
        __syncthreads();
    }
    if (threadIdx.x == 0) g_blk[blockIdx.x] = sh[0];
}
__global__ void __launch_bounds__(256) scan2_kernel() {
    __shared__ int sh[256];
    int v = g_blk[threadIdx.x];
    sh[threadIdx.x] = v;
    __syncthreads();
    for (int d = 1; d < 256; d <<= 1) {
        int t = (threadIdx.x >= d) ? sh[threadIdx.x - d] : 0;
        __syncthreads();
        sh[threadIdx.x] += t;
        __syncthreads();
    }
    g_blk[threadIdx.x] = sh[threadIdx.x] - v;   // exclusive
}
__global__ void __launch_bounds__(256) scan3_kernel() {
    __shared__ int sh[256];
    int i = blockIdx.x * 256 + threadIdx.x;
    int v = g_cnt[i];
    sh[threadIdx.x] = v;
    __syncthreads();
    for (int d = 1; d < 256; d <<= 1) {
        int t = (threadIdx.x >= d) ? sh[threadIdx.x - d] : 0;
        __syncthreads();
        sh[threadIdx.x] += t;
        __syncthreads();
    }
    int st = g_blk[blockIdx.x] + sh[threadIdx.x] - v;     // exclusive
    g_start[i]  = st;
    g_cursor[i] = st;
}

// ---------------------------------------------------------------------------
// Kernel 4: reorder edges into CSR order (packed col + val bits)
// ---------------------------------------------------------------------------
__global__ void __launch_bounds__(256) reorder_kernel(const void* __restrict__ rowp,
                                                      const void* __restrict__ colp,
                                                      const float* __restrict__ vals) {
    const bool is64 = (g_or_hi == 0u);
    int e = blockIdx.x * blockDim.x + threadIdx.x;
    int r = load_idx(rowp, e, is64);
    int c = load_idx(colp, e, is64);
    int pos = atomicAdd(&g_cursor[r], 1);
    g_edges[pos] = make_uint2((unsigned)c, __float_as_uint(vals[e]));
}

// ---------------------------------------------------------------------------
// Kernel 5: round x fp32 -> fp16 (halves SpMM gather traffic)
// ---------------------------------------------------------------------------
__global__ void __launch_bounds__(256) cvt_x_kernel(const float* __restrict__ x) {
    const size_t n4 = (size_t)N_NODES * DIM / 4;
    for (size_t i = (size_t)blockIdx.x * blockDim.x + threadIdx.x; i < n4;
         i += (size_t)gridDim.x * blockDim.x) {
        float4 v = reinterpret_cast<const float4*>(x)[i];
        unsigned short h[4];
        h[0] = __half_as_ushort(__float2half_rn(v.x));
        h[1] = __half_as_ushort(__float2half_rn(v.y));
        h[2] = __half_as_ushort(__float2half_rn(v.z));
        h[3] = __half_as_ushort(__float2half_rn(v.w));
        uint2 hp;
        hp.x = (uint32_t)h[0] | ((uint32_t)h[1] << 16);
        hp.y = (uint32_t)h[2] | ((uint32_t)h[3] << 16);
        *reinterpret_cast<uint2*>(g_xhf + i * 4) = hp;
    }
}

// ---------------------------------------------------------------------------
// Kernel 6: gather SpMM on fp16 x. One warp per row, 4-edge unroll.
// Accumulate fp32; epilogue writes fp16 [hi|lo] split into g_Yhf.
// ---------------------------------------------------------------------------
__device__ __forceinline__ void acc_chunk(float4& a, uint2 h, float v) {
    float2 f0 = __half22float2(*reinterpret_cast<__half2*>(&h.x));
    float2 f1 = __half22float2(*reinterpret_cast<__half2*>(&h.y));
    a.x += v * f0.x; a.y += v * f0.y;
    a.z += v * f1.x; a.w += v * f1.y;
}

__global__ void __launch_bounds__(256) spmm_kernel() {
    const int row  = blockIdx.x * 8 + (threadIdx.x >> 5);
    const int lane = threadIdx.x & 31;
    const int s = g_start[row];
    const int e = s + g_cnt[row];

    float4 acc[4];
    #pragma unroll
    for (int j = 0; j < 4; j++) acc[j] = make_float4(0.f, 0.f, 0.f, 0.f);

    int i = s;
    for (; i + 3 < e; i += 4) {
        uint2 p[4];
        #pragma unroll
        for (int q = 0; q < 4; q++) p[q] = g_edges[i + q];
        uint2 t[4][4];
        #pragma unroll
        for (int q = 0; q < 4; q++) {
            const uint2* xs = reinterpret_cast<const uint2*>(g_xhf + (size_t)p[q].x * DIM);
            #pragma unroll
            for (int j = 0; j < 4; j++) t[q][j] = xs[lane + 32 * j];
        }
        #pragma unroll
        for (int q = 0; q < 4; q++) {
            float v = __uint_as_float(p[q].y);
            #pragma unroll
            for (int j = 0; j < 4; j++) acc_chunk(acc[j], t[q][j], v);
        }
    }
    for (; i + 1 < e; i += 2) {
        uint2 p0 = g_edges[i], p1 = g_edges[i + 1];
        const uint2* x0 = reinterpret_cast<const uint2*>(g_xhf + (size_t)p0.x * DIM);
        const uint2* x1 = reinterpret_cast<const uint2*>(g_xhf + (size_t)p1.x * DIM);
        float v0 = __uint_as_float(p0.y), v1 = __uint_as_float(p1.y);
        uint2 t0[4], t1[4];
        #pragma unroll
        for (int j = 0; j < 4; j++) { t0[j] = x0[lane + 32 * j]; t1[j] = x1[lane + 32 * j]; }
        #pragma unroll
        for (int j = 0; j < 4; j++) { acc_chunk(acc[j], t0[j], v0); acc_chunk(acc[j], t1[j], v1); }
    }
    if (i < e) {
        uint2 p = g_edges[i];
        const uint2* xs = reinterpret_cast<const uint2*>(g_xhf + (size_t)p.x * DIM);
        float v = __uint_as_float(p.y);
        #pragma unroll
        for (int j = 0; j < 4; j++) {
            uint2 t = xs[lane + 32 * j];
            acc_chunk(acc[j], t, v);
        }
    }

    // epilogue: split fp32 -> fp16 hi/lo, write both halves
    __half* dst = g_Yhf + (size_t)row * K2;
    #pragma unroll
    for (int j = 0; j < 4; j++) {
        int c4 = lane + 32 * j;
        float f[4] = {acc[j].x, acc[j].y, acc[j].z, acc[j].w};
        unsigned short h[4], l[4];
        #pragma unroll
        for (int k = 0; k < 4; k++) {
            __half hb = __float2half_rn(f[k]);
            __half lb = __float2half_rn(f[k] - __half2float(hb));
            h[k] = __half_as_ushort(hb);
            l[k] = __half_as_ushort(lb);
        }
        uint2 hp, lp;
        hp.x = (uint32_t)h[0] | ((uint32_t)h[1] << 16);
        hp.y = (uint32_t)h[2] | ((uint32_t)h[3] << 16);
        lp.x = (uint32_t)l[0] | ((uint32_t)l[1] << 16);
        lp.y = (uint32_t)l[2] | ((uint32_t)l[3] << 16);
        *reinterpret_cast<uint2*>(dst + 4 * c4)       = hp;
        *reinterpret_cast<uint2*>(dst + 512 + 4 * c4) = lp;
    }
}

// ---------------------------------------------------------------------------
// Kernel 7: round W fp32 -> fp16
// ---------------------------------------------------------------------------
__global__ void __launch_bounds__(256) cvt_W_kernel(const float* __restrict__ W) {
    const size_t n4 = (size_t)DIM * (DIM / 4);
    for (size_t i = (size_t)blockIdx.x * blockDim.x + threadIdx.x; i < n4;
         i += (size_t)gridDim.x * blockDim.x) {
        float4 v = reinterpret_cast<const float4*>(W)[i];
        unsigned short h[4];
        h[0] = __half_as_ushort(__float2half_rn(v.x));
        h[1] = __half_as_ushort(__float2half_rn(v.y));
        h[2] = __half_as_ushort(__float2half_rn(v.z));
        h[3] = __half_as_ushort(__float2half_rn(v.w));
        uint2 hp;
        hp.x = (uint32_t)h[0] | ((uint32_t)h[1] << 16);
        hp.y = (uint32_t)h[2] | ((uint32_t)h[3] << 16);
        *reinterpret_cast<uint2*>(g_Whf + i * 4) = hp;
    }
}

// ---------------------------------------------------------------------------
// Kernel 8: mma.sync fp16 GEMM   out[65536,512] = (Yhi+Ylo) @ W16^T
// CTA tile 128x128, BK=32, 8 warps (4x2) each 32x64.
// 3-stage cp.async pipeline, one __syncthreads per iteration.
// ---------------------------------------------------------------------------
#define RSTR  80               // padded smem row stride (conflict-free ldmatrix)
#define NSTAGE 3

__device__ __forceinline__ uint32_t smem_u32(const void* p) {
    uint32_t a;
    asm("{ .reg .u64 t; cvta.to.shared.u64 t, %1; cvt.u32.u64 %0, t; }"
        : "=r"(a) : "l"(p));
    return a;
}
__device__ __forceinline__ void cp16(uint32_t smem, const void* gmem) {
    asm volatile("cp.async.cg.shared.global [%0], [%1], 16;"
                 :: "r"(smem), "l"(gmem));
}
__device__ __forceinline__ void ldsm4(uint32_t* r, uint32_t addr) {
    asm volatile("ldmatrix.sync.aligned.m8n8.x4.shared.b16 {%0,%1,%2,%3}, [%4];"
                 : "=r"(r[0]), "=r"(r[1]), "=r"(r[2]), "=r"(r[3]) : "r"(addr));
}
__device__ __forceinline__ void mma16816(float* d, const uint32_t* a,
                                         uint32_t b0, uint32_t b1) {
    asm volatile(
        "mma.sync.aligned.m16n8k16.row.col.f32.f16.f16.f32 "
        "{%0,%1,%2,%3}, {%4,%5,%6,%7}, {%8,%9}, {%0,%1,%2,%3};"
        : "+f"(d[0]), "+f"(d[1]), "+f"(d[2]), "+f"(d[3])
        : "r"(a[0]), "r"(a[1]), "r"(a[2]), "r"(a[3]), "r"(b0), "r"(b1));
}

__global__ void __launch_bounds__(256) gemm_mma_kernel(float* __restrict__ out) {
    __shared__ char sA[NSTAGE][128 * RSTR];
    __shared__ char sB[NSTAGE][128 * RSTR];

    const int tid  = threadIdx.x;
    const int wid  = tid >> 5;
    const int lane = tid & 31;
    const int bn   = blockIdx.x;   // 0..3  (N tiles of 128)
    const int bm   = blockIdx.y;   // 0..511 (M tiles of 128)

    const int wm = (wid >> 1) * 32;
    const int wn = (wid & 1) * 64;

    int r0 = tid >> 2, c0 = (tid & 3) * 16;
    int r1 = (tid + 256) >> 2, c1 = c0;
    const char* Ag0 = (const char*)(g_Yhf + (size_t)(bm * 128 + r0) * K2) + c0;
    const char* Ag1 = (const char*)(g_Yhf + (size_t)(bm * 128 + r1) * K2) + c1;
    const char* Bg0 = (const char*)(g_Whf + (size_t)(bn * 128 + r0) * DIM) + c0;
    const char* Bg1 = (const char*)(g_Whf + (size_t)(bn * 128 + r1) * DIM) + c1;
    const int sOff0 = r0 * RSTR + c0, sOff1 = r1 * RSTR + c1;

    const uint32_t saA = smem_u32(sA[0]);
    const uint32_t saB = smem_u32(sB[0]);
    const uint32_t STG = 128 * RSTR;

    const int lrow = lane & 15;
    const int lhalf = ((lane >> 4) & 1) * 16;
    uint32_t rowA[2], rowB[4];
    #pragma unroll
    for (int mt = 0; mt < 2; mt++)
        rowA[mt] = (uint32_t)((wm + mt * 16 + lrow) * RSTR + lhalf);
    #pragma unroll
    for (int nt = 0; nt < 4; nt++)
        rowB[nt] = (uint32_t)((wn + nt * 16 + lrow) * RSTR + lhalf);

    float acc[2][8][4];
    #pragma unroll
    for (int mt = 0; mt < 2; mt++)
        #pragma unroll
        for (int j = 0; j < 8; j++)
            #pragma unroll
            for (int q = 0; q < 4; q++) acc[mt][j][q] = 0.f;

    // chunk i (0..31): half = i>>4 (A hi/lo), c = i&15 -> k offset.
    auto issue_loads = [&](int i, int s) {
        const int half = i >> 4, c = i & 15;
        const int akB = (half * 512 + c * 32) * 2;
        const int bkB = (c * 32) * 2;
        uint32_t dA = saA + s * STG;
        uint32_t dB = saB + s * STG;
        cp16(dA + sOff0, Ag0 + akB);
        cp16(dA + sOff1, Ag1 + akB);
        cp16(dB + sOff0, Bg0 + bkB);
        cp16(dB + sOff1, Bg1 + bkB);
        asm volatile("cp.async.commit_group;");
    };

    issue_loads(0, 0);
    issue_loads(1, 1);

    #pragma unroll 1
    for (int i = 0; i < 32; i++) {
        const int s = i % NSTAGE;
        if (i < 31) asm volatile("cp.async.wait_group 1;");
        else        asm volatile("cp.async.wait_group 0;");
        __syncthreads();
        if (i + 2 < 32) issue_loads(i + 2, (i + 2) % NSTAGE);

        const uint32_t bA = saA + s * STG;
        const uint32_t bB = saB + s * STG;

        #pragma unroll
        for (int kt = 0; kt < 2; kt++) {
            uint32_t af[2][4], bf[4][4];
            #pragma unroll
            for (int mt = 0; mt < 2; mt++)
                ldsm4(af[mt], bA + rowA[mt] + kt * 32);
            #pragma unroll
            for (int nt = 0; nt < 4; nt++)
                ldsm4(bf[nt], bB + rowB[nt] + kt * 32);
            #pragma unroll
            for (int mt = 0; mt < 2; mt++)
                #pragma unroll
                for (int nt = 0; nt < 4; nt++) {
                    mma16816(acc[mt][nt * 2 + 0], af[mt], bf[nt][0], bf[nt][2]);
                    mma16816(acc[mt][nt * 2 + 1], af[mt], bf[nt][1], bf[nt][3]);
                }
        }
    }

    const int erow = lane >> 2, ecol = (lane & 3) * 2;
    #pragma unroll
    for (int mt = 0; mt < 2; mt++) {
        float* o0 = out + (size_t)(bm * 128 + wm + mt * 16 + erow) * DIM
                        + bn * 128 + wn + ecol;
        float* o1 = o0 + 8 * DIM;
        #pragma unroll
        for (int j = 0; j < 8; j++) {
            *reinterpret_cast<float2*>(o0 + j * 8) =
                make_float2(acc[mt][j][0], acc[mt][j][1]);
            *reinterpret_cast<float2*>(o1 + j * 8) =
                make_float2(acc[mt][j][2], acc[mt][j][3]);
        }
    }
}

// ---------------------------------------------------------------------------
// kernel_launch: inputs (metadata order): x, weight, row, col, vals
// ---------------------------------------------------------------------------
extern "C" void kernel_launch(void* const* d_in, const int* in_sizes, int n_in,
                              void* d_out, int out_size) {
    const float* x      = (const float*)d_in[0];
    const float* weight = (const float*)d_in[1];
    const void*  row    = d_in[2];
    const void*  col    = d_in[3];
    const float* vals   = (const float*)d_in[4];
    float* out = (float*)d_out;

    (void)in_sizes; (void)n_in; (void)out_size;

    // CSR build
    init_kernel<<<N_NODES / (256 * 4), 256>>>();
    detect_kernel<<<128, 256>>>((const unsigned int*)row);
    hist_kernel<<<N_EDGES / 256, 256>>>(row);
    scan1_kernel<<<256, 256>>>();
    scan2_kernel<<<1, 256>>>();
    scan3_kernel<<<256, 256>>>();
    reorder_kernel<<<N_EDGES / 256, 256>>>(row, col, vals);

    // x -> fp16, W -> fp16
    cvt_x_kernel<<<2048, 256>>>(x);
    cvt_W_kernel<<<256, 256>>>(weight);

    // gather SpMM (fp16 x) -> g_Yhf (fp16 hi/lo, fused split)
    spmm_kernel<<<N_NODES / 8, 256>>>();

    // out = (Yhi+Ylo) @ W16^T on tensor cores (fp16 mma, 2-term split)
    dim3 grid(4, 512);
    gemm_mma_kernel<<<grid, 256>>>(out);
}